// round 16
// baseline (speedup 1.0000x reference)
#include <cuda_runtime.h>
#include <math.h>

#define D_     196
#define NCH_   64
#define H_     8
#define DH_    64
#define INNER_ 512
#define MLP_   784
#define SEQ_   65
#define NG_QKV 384   // 1536/4
#define NG_D   49    // 196/4
#define NG_MLP 196   // 784/4
#define GRID_  100
#define NT_    512

// ---- scratch (__device__ globals; no allocations allowed) ----
__device__ float  g_a[NCH_ * D_];
__device__ float4 g_xatt4[SEQ_ * NG_D];
__device__ float4 g_qkv4[SEQ_ * NG_QKV];    // q(pre-scaled)|k|v
__device__ unsigned g_flag[GRID_];          // per-block arrival generations (monotonic)
__device__ unsigned g_gen;                  // barrier generation (monotonic)

__device__ __forceinline__ void fma4(float4& a, float h, const float4& w) {
    a.x += h * w.x; a.y += h * w.y; a.z += h * w.z; a.w += h * w.w;
}
__device__ __forceinline__ void add4(float4& a, const float4& b) {
    a.x += b.x; a.y += b.y; a.z += b.z; a.w += b.w;
}
__device__ __forceinline__ float gelu_exact(float v) {
    return 0.5f * v * (1.f + erff(v * 0.70710678118654752f));
}

// grid-wide barrier, flag-array version.
// Arrival: each block release-stores flag[b] = gen+1 (no atomic contention).
// Block 0's warp 0 min-reduces all flags in parallel, then bumps g_gen.
// Monotonic generations -> deterministic across graph replays.
// Safe: gridDim.x (100) <= #SMs (148), 1 block/SM -> all co-resident.
__device__ __forceinline__ void gsync() {
    __syncthreads();
    if (threadIdx.x < 32) {
        const int lane = threadIdx.x;
        unsigned gen = *(volatile unsigned*)&g_gen;   // all lanes read same line
        if (lane == 0) {
            __threadfence();                           // release all prior writes
            *(volatile unsigned*)&g_flag[blockIdx.x] = gen + 1u;
        }
        if (blockIdx.x == 0) {
            // aggregate: wait until every block's flag reaches gen+1
            for (;;) {
                unsigned mn = 0xffffffffu;
                #pragma unroll
                for (int i = 0; i < 4; i++) {
                    int idx = lane + 32 * i;
                    if (idx < GRID_) {
                        unsigned f = *(volatile unsigned*)&g_flag[idx];
                        mn = (f < mn) ? f : mn;
                    }
                }
                #pragma unroll
                for (int o = 16; o; o >>= 1) {
                    unsigned other = __shfl_down_sync(0xffffffffu, mn, o);
                    mn = (other < mn) ? other : mn;
                }
                mn = __shfl_sync(0xffffffffu, mn, 0);
                if (mn > gen) break;
                __nanosleep(32);
            }
            if (lane == 0) {
                __threadfence();                       // order flag reads before release
                *(volatile unsigned*)&g_gen = gen + 1u;
            }
        } else if (lane == 0) {
            while (*(volatile unsigned*)&g_gen == gen) { __nanosleep(32); }
        }
        if (lane == 0) __threadfence();                // acquire
    }
    __syncthreads();
}

__global__ __launch_bounds__(NT_, 1) void k_fused(
    const float* __restrict__ x, const float* __restrict__ tokens,
    const float* __restrict__ x_pe, const float* __restrict__ conv_k,
    const float* __restrict__ bn_g, const float* __restrict__ bn_b,
    const float* __restrict__ bn_rm, const float* __restrict__ bn_rv,
    const float* __restrict__ fc_w1, const float* __restrict__ fc_w2,
    const float* __restrict__ ln1_g, const float* __restrict__ ln1_b,
    const float4* __restrict__ wqkv4,
    const float4* __restrict__ wout4, const float4* __restrict__ bout4,
    const float4* __restrict__ ln2g4, const float4* __restrict__ ln2b4,
    const float4* __restrict__ ffw1_4, const float4* __restrict__ ffb1_4,
    const float4* __restrict__ ffw2_4, const float4* __restrict__ ffb2_4,
    float4* __restrict__ out4)
{
    __shared__ __align__(16) char sm[20160];
    const int tid = threadIdx.x;
    const int b   = blockIdx.x;

    // ================= PHASE A: LN1 + QKV (blocks 0..98) + gating (99) =================
    if (b < 99) {
        float*  hs   = (float*)sm;                 // 2*196 floats (ends 1568)
        float4* red  = (float4*)(sm + 1600);       // 3 slices * 128 gl * 2 rows (12288 B)
        float*  mrow = (float*)(sm + 13888);       // 2
        float*  rrow = (float*)(sm + 13896);       // 2

        const int tile  = b / 3;
        const int chunk = b - tile * 3;
        const int base  = tile * 2;                // rows base, base+1

        if (tid < 2 * D_) {
            int r = tid / D_, c = tid - r * D_;
            int row = base + r;
            hs[tid] = (row < SEQ_) ? x[row * D_ + c] : 0.f;
        }
        __syncthreads();

        const int warp = tid >> 5, lane = tid & 31;
        if (warp < 2) {
            float s1 = 0.f, s2 = 0.f;
            #pragma unroll
            for (int i = 0; i < 7; i++) {
                int c = lane + 32 * i;
                if (c < D_) { float v = hs[warp * D_ + c]; s1 += v; s2 += v * v; }
            }
            #pragma unroll
            for (int o = 16; o; o >>= 1) {
                s1 += __shfl_down_sync(0xffffffffu, s1, o);
                s2 += __shfl_down_sync(0xffffffffu, s2, o);
            }
            if (lane == 0) {
                float mean = s1 * (1.f / 196.f);
                float var  = s2 * (1.f / 196.f) - mean * mean;
                mrow[warp] = mean; rrow[warp] = rsqrtf(var + 1e-5f);
            }
        }
        __syncthreads();
        if (tid < 2 * D_) {
            int r = tid / D_, c = tid - r * D_;
            hs[tid] = (hs[tid] - mrow[r]) * rrow[r] * ln1_g[c] + ln1_b[c];
        }
        __syncthreads();

        const int gl = tid & 127;
        const int g  = chunk * 128 + gl;     // < 384
        const int s  = tid >> 7;             // K-slice 0..3, each 49
        float4 a0 = make_float4(0.f, 0.f, 0.f, 0.f);
        float4 a1 = make_float4(0.f, 0.f, 0.f, 0.f);

        const int kb = s * 49;
        const float4* W = wqkv4 + kb * NG_QKV + g;
        #pragma unroll 7
        for (int k = 0; k < 49; k++) {
            float4 w = W[k * NG_QKV];
            fma4(a0, hs[kb + k], w);
            fma4(a1, hs[D_ + kb + k], w);
        }
        if (s > 0) {
            red[((s - 1) * 128 + gl) * 2 + 0] = a0;
            red[((s - 1) * 128 + gl) * 2 + 1] = a1;
        }
        __syncthreads();
        if (s == 0) {
            float sc = (g < 128) ? 0.125f : 1.f;   // q pre-scale DH^-0.5
            #pragma unroll
            for (int ss = 0; ss < 3; ss++) {
                add4(a0, red[(ss * 128 + gl) * 2 + 0]);
                add4(a1, red[(ss * 128 + gl) * 2 + 1]);
            }
            a0.x *= sc; a0.y *= sc; a0.z *= sc; a0.w *= sc;
            a1.x *= sc; a1.y *= sc; a1.z *= sc; a1.w *= sc;
            if (base < SEQ_)     g_qkv4[base * NG_QKV + g]       = a0;
            if (base + 1 < SEQ_) g_qkv4[(base + 1) * NG_QKV + g] = a1;
        }
    } else {
        // ---------------- gating (block 99) ----------------
        float* b1s = (float*)sm;              // 64
        float* b2s = (float*)(sm + 256);      // 64
        float* hid = (float*)(sm + 512);      // 12
        float* cs  = (float*)(sm + 576);      // 64

        const int warp = tid >> 5, lane = tid & 31;
        const float k0 = conv_k[3], k1 = conv_k[4], k2 = conv_k[5];
        const float rm  = bn_rm[0];
        const float inv = rsqrtf(bn_rv[0] + 1e-5f) * bn_g[0];
        const float bb  = bn_b[0];

        for (int ch = warp; ch < NCH_; ch += 16) {
            const float* row = x_pe + ch * D_;
            float s = 0.f;
            for (int d = lane; d < D_; d += 32) {
                float xm = (d > 0)      ? row[d - 1] : 0.f;
                float xc = row[d];
                float xp = (d < D_ - 1) ? row[d + 1] : 0.f;
                float conv = k0 * xm + k1 * xc + k2 * xp;
                float bn = (conv - rm) * inv + bb;
                float av = fmaxf(bn, 0.f);
                g_a[ch * D_ + d] = av;
                s += av;
            }
            #pragma unroll
            for (int o = 16; o; o >>= 1) s += __shfl_down_sync(0xffffffffu, s, o);
            if (lane == 0) b1s[ch] = s * (1.f / 196.f);
        }
        __syncthreads();

        if (tid < NCH_) {
            const float bi = b1s[tid];
            float mx = -1e30f, mn = 1e30f;
            int cnt_nonpos = 0, rank = 0;
            #pragma unroll 8
            for (int j = 0; j < NCH_; j++) {
                float bj = b1s[j];
                mx = fmaxf(mx, bj); mn = fminf(mn, bj);
                if (bj <= 0.f) cnt_nonpos++;
                if (bj < bi || (bj == bi && j < tid)) rank++;
            }
            int middle = (mx < 0.f || mn > 0.f) ? 32 : (mx > 0.f ? cnt_nonpos : 0);
            float b2;
            if (rank < middle) {
                float ls = (float)middle;
                b2 = bi - 1.f / (1.f + powf(ls, bi));
            } else {
                float le = (float)(NCH_ - middle);
                b2 = bi + 1.f / (1.f + powf(le, -bi));
            }
            b2s[tid] = b2;
        }
        __syncthreads();
        if (tid < 12) {
            float s = 0.f;
            #pragma unroll 8
            for (int i = 0; i < NCH_; i++) s += b2s[i] * fc_w1[i * 12 + tid];
            hid[tid] = fmaxf(s, 0.f);
        }
        __syncthreads();
        if (tid < NCH_) {
            float s = 0.f;
            #pragma unroll
            for (int j = 0; j < 12; j++) s += hid[j] * fc_w2[j * NCH_ + tid];
            cs[tid] = 1.f / (1.f + expf(-s));
        }
        __syncthreads();
        float* xatt = (float*)g_xatt4;
        for (int idx = tid; idx < NCH_ * D_; idx += NT_)
            xatt[idx] = g_a[idx] * cs[idx / D_];
        for (int d = tid; d < D_; d += NT_)
            xatt[NCH_ * D_ + d] = tokens[d];
    }
    gsync();   // the ONLY grid barrier

    // ================= PHASE B: per-row pipeline (blocks 0..64) =================
    if (b >= SEQ_) return;
    const int n = b;
    const float* qkv = (const float*)g_qkv4;

    float*  qs    = (float*)sm;                // 512 f          [0,2048)
    float*  scs   = (float*)(sm + 2048);       // 8*66 f         [2048,4160)
    float*  smaxp = (float*)(sm + 4160);       // 8
    float*  sinvp = (float*)(sm + 4192);       // 8
    float*  os    = (float*)(sm + 4224);       // 512 f          [4224,6272)
    float4* red   = (float4*)(sm + 6272);      // 7*49 f4        [6272,11760)
    float4* x2s   = (float4*)(sm + 11760);     // 49 f4          [11760,12544)
    float4* h2s   = (float4*)(sm + 12544);     // 49 f4          [12544,13328)
    float*  p1    = (float*)(sm + 13328);      // 49
    float*  p2    = (float*)(sm + 13524);      // 49
    float*  stats = (float*)(sm + 13720);      // 2
    float4* ts4   = (float4*)(sm + 13744);     // 196 f4         [13744,16880)
    float4* red1  = (float4*)(sm + 16880);     // 196 f4         [16880,20016)

    // ---- attention: head h = tid>>6, lane-within-head d = tid&63 ----
    const int h = tid >> 6, d = tid & 63;
    qs[tid] = qkv[n * 1536 + tid];            // q row (pre-scaled)
    __syncthreads();

    const float* qh = qs + h * DH_;
    {
        const float4* kr = (const float4*)(qkv + d * 1536 + INNER_ + h * DH_);
        float s = 0.f;
        #pragma unroll
        for (int i = 0; i < 16; i++) {
            float4 k4 = kr[i];
            s += qh[4*i] * k4.x + qh[4*i+1] * k4.y + qh[4*i+2] * k4.z + qh[4*i+3] * k4.w;
        }
        scs[h * 66 + d] = s;
        if (d == 0) {
            const float4* kr2 = (const float4*)(qkv + 64 * 1536 + INNER_ + h * DH_);
            float s2 = 0.f;
            #pragma unroll
            for (int i = 0; i < 16; i++) {
                float4 k4 = kr2[i];
                s2 += qh[4*i] * k4.x + qh[4*i+1] * k4.y + qh[4*i+2] * k4.z + qh[4*i+3] * k4.w;
            }
            scs[h * 66 + 64] = s2;
        }
    }
    __syncthreads();
    if (d < 32) {
        float m = fmaxf(scs[h * 66 + d], scs[h * 66 + d + 32]);
        if (d == 0) m = fmaxf(m, scs[h * 66 + 64]);
        #pragma unroll
        for (int o = 16; o; o >>= 1) m = fmaxf(m, __shfl_down_sync(0xffffffffu, m, o));
        if (d == 0) smaxp[h] = m;
    }
    __syncthreads();
    {
        float mx = smaxp[h];
        scs[h * 66 + d] = expf(scs[h * 66 + d] - mx);
        if (d == 0) scs[h * 66 + 64] = expf(scs[h * 66 + 64] - mx);
    }
    __syncthreads();
    if (d < 32) {
        float s = scs[h * 66 + d] + scs[h * 66 + d + 32];
        if (d == 0) s += scs[h * 66 + 64];
        #pragma unroll
        for (int o = 16; o; o >>= 1) s += __shfl_down_sync(0xffffffffu, s, o);
        if (d == 0) sinvp[h] = 1.f / s;
    }
    __syncthreads();
    {
        const float* vb = qkv + 2 * INNER_ + h * DH_ + d;
        const float* p  = scs + h * 66;
        float acc = 0.f;
        #pragma unroll 8
        for (int m = 0; m < SEQ_; m++) acc += p[m] * vb[m * 1536];
        os[tid] = acc * sinvp[h];
    }
    __syncthreads();

    // ---- out-proj (K=512, 8 warp-aligned slices of 64) + residuals + LN2 ----
    // s8 = tid>>6 (slice), g = tid&63 (<49 active): warps never straddle slices,
    // weight loads are one contiguous 784B segment per warp.
    const int s8 = tid >> 6;                   // 0..7
    const int g  = tid & 63;                   // <49 active
    const bool act = (g < NG_D);
    float4 vacc = make_float4(0.f, 0.f, 0.f, 0.f);
    if (act) {
        const int kb = s8 * 64;
        const float4* W = wout4 + kb * NG_D + g;
        const float* hb = os + kb;
        #pragma unroll 8
        for (int k = 0; k < 64; k++) fma4(vacc, hb[k], W[k * NG_D]);
        if (s8 > 0) red[(s8 - 1) * NG_D + g] = vacc;
    }
    __syncthreads();
    if (act && s8 == 0) {
        #pragma unroll
        for (int ss = 0; ss < 7; ss++) add4(vacc, red[ss * NG_D + g]);
        float4 bo = bout4[g];
        float4 xv = ((const float4*)x)[n * NG_D + g];
        float4 xa = g_xatt4[n * NG_D + g];
        vacc.x += bo.x + xv.x + xa.x;
        vacc.y += bo.y + xv.y + xa.y;
        vacc.z += bo.z + xv.z + xa.z;
        vacc.w += bo.w + xv.w + xa.w;
        x2s[g] = vacc;
        p1[g] = vacc.x + vacc.y + vacc.z + vacc.w;
        p2[g] = vacc.x*vacc.x + vacc.y*vacc.y + vacc.z*vacc.z + vacc.w*vacc.w;
    }
    __syncthreads();
    if (tid < 32) {
        float t1 = 0.f, t2 = 0.f;
        for (int i = tid; i < NG_D; i += 32) { t1 += p1[i]; t2 += p2[i]; }
        #pragma unroll
        for (int o = 16; o; o >>= 1) {
            t1 += __shfl_down_sync(0xffffffffu, t1, o);
            t2 += __shfl_down_sync(0xffffffffu, t2, o);
        }
        if (tid == 0) {
            float mean = t1 * (1.f / 196.f);
            float var  = t2 * (1.f / 196.f) - mean * mean;
            stats[0] = mean; stats[1] = rsqrtf(var + 1e-5f);
        }
    }
    __syncthreads();
    if (act && s8 == 0) {
        float m = stats[0], rs = stats[1];
        float4 v = x2s[g], gg = ln2g4[g], bb = ln2b4[g], hh;
        hh.x = (v.x - m) * rs * gg.x + bb.x;
        hh.y = (v.y - m) * rs * gg.y + bb.y;
        hh.z = (v.z - m) * rs * gg.z + bb.z;
        hh.w = (v.w - m) * rs * gg.w + bb.w;
        h2s[g] = hh;
    }
    __syncthreads();

    // ---- FF1 (K=196, 2 warp-aligned slices of 98) + GELU ----
    // s1 = tid>>8 (slice), gg = tid&255 (<196 active)
    float4 facc = make_float4(0.f, 0.f, 0.f, 0.f);
    {
        const int s1 = tid >> 8;               // 0..1
        const int gg = tid & 255;              // <196 active
        if (gg < NG_MLP) {
            const float* hh = (const float*)h2s;   // 196 floats
            const int kb = s1 * 98;
            const float4* W = ffw1_4 + kb * NG_MLP + gg;
            #pragma unroll 7
            for (int k = 0; k < 98; k++) fma4(facc, hh[kb + k], W[k * NG_MLP]);
            if (s1 == 1) red1[gg] = facc;
        }
    }
    __syncthreads();
    if (tid < NG_MLP) {
        add4(facc, red1[tid]);
        float4 fb = ffb1_4[tid], t;
        t.x = gelu_exact(facc.x + fb.x);
        t.y = gelu_exact(facc.y + fb.y);
        t.z = gelu_exact(facc.z + fb.z);
        t.w = gelu_exact(facc.w + fb.w);
        ts4[tid] = t;
    }
    __syncthreads();

    // ---- FF2 (K=784, 8 warp-aligned slices of 98) + residual -> out ----
    float4 oacc = make_float4(0.f, 0.f, 0.f, 0.f);
    if (act) {
        const int kb = s8 * 98;
        const float* tf = (const float*)ts4;   // 784 floats
        const float4* W = ffw2_4 + kb * NG_D + g;
        #pragma unroll 7
        for (int k = 0; k < 98; k++) fma4(oacc, tf[kb + k], W[k * NG_D]);
        if (s8 > 0) red[(s8 - 1) * NG_D + g] = oacc;
    }
    __syncthreads();
    if (act && s8 == 0) {
        #pragma unroll
        for (int ss = 0; ss < 7; ss++) add4(oacc, red[ss * NG_D + g]);
        float4 fb = ffb2_4[g], x2 = x2s[g];
        oacc.x += fb.x + x2.x; oacc.y += fb.y + x2.y;
        oacc.z += fb.z + x2.z; oacc.w += fb.w + x2.w;
        out4[n * NG_D + g] = oacc;
    }
}

// ============================================================
extern "C" void kernel_launch(void* const* d_in, const int* in_sizes, int n_in,
                              void* d_out, int out_size)
{
    const float* x      = (const float*)d_in[0];
    const float* tokens = (const float*)d_in[1];
    const float* x_pe   = (const float*)d_in[2];
    const float* conv_k = (const float*)d_in[3];
    const float* bn_g   = (const float*)d_in[4];
    const float* bn_b   = (const float*)d_in[5];
    const float* bn_rm  = (const float*)d_in[6];
    const float* bn_rv  = (const float*)d_in[7];
    const float* fc_w1  = (const float*)d_in[8];
    const float* fc_w2  = (const float*)d_in[9];
    const float* ln1_g  = (const float*)d_in[10];
    const float* ln1_b  = (const float*)d_in[11];
    const float* ln2_g  = (const float*)d_in[12];
    const float* ln2_b  = (const float*)d_in[13];
    const float* w_qkv  = (const float*)d_in[14];
    const float* w_out  = (const float*)d_in[15];
    const float* b_out  = (const float*)d_in[16];
    const float* ff_w1  = (const float*)d_in[17];
    const float* ff_b1  = (const float*)d_in[18];
    const float* ff_w2  = (const float*)d_in[19];
    const float* ff_b2  = (const float*)d_in[20];

    k_fused<<<GRID_, NT_>>>(x, tokens, x_pe, conv_k, bn_g, bn_b, bn_rm, bn_rv,
                            fc_w1, fc_w2, ln1_g, ln1_b,
                            (const float4*)w_qkv,
                            (const float4*)w_out, (const float4*)b_out,
                            (const float4*)ln2_g, (const float4*)ln2_b,
                            (const float4*)ff_w1, (const float4*)ff_b1,
                            (const float4*)ff_w2, (const float4*)ff_b2,
                            (float4*)d_out);
}

// round 17
// speedup vs baseline: 1.0816x; 1.0816x over previous
#include <cuda_runtime.h>
#include <math.h>

#define D_     196
#define NCH_   64
#define H_     8
#define DH_    64
#define INNER_ 512
#define MLP_   784
#define SEQ_   65
#define NG_QKV 384   // 1536/4
#define NG_D   49    // 196/4
#define NG_MLP 196   // 784/4
#define GRID_  131
#define NT_    512

// ---- scratch (__device__ globals; no allocations allowed) ----
__device__ float  g_a[NCH_ * D_];
__device__ float4 g_xatt4[SEQ_ * NG_D];
__device__ float4 g_qkv4[SEQ_ * NG_QKV];    // q(pre-scaled)|k|v
__device__ float4 g_p1[SEQ_ * NG_D];        // helper outproj partials
__device__ float4 g_h2g[SEQ_ * NG_D];       // LN2 output broadcast
__device__ float4 g_p2[SEQ_ * NG_D];        // helper FF2 partials
__device__ unsigned g_fA[SEQ_];             // flags (monotonic generations)
__device__ unsigned g_fB[SEQ_];
__device__ unsigned g_fC[SEQ_];
__device__ unsigned g_cnt;                  // barrier arrival counter (self-resetting)
__device__ unsigned g_gen;                  // barrier generation (monotonic)

__device__ __forceinline__ void fma4(float4& a, float h, const float4& w) {
    a.x += h * w.x; a.y += h * w.y; a.z += h * w.z; a.w += h * w.w;
}
__device__ __forceinline__ void add4(float4& a, const float4& b) {
    a.x += b.x; a.y += b.y; a.z += b.z; a.w += b.w;
}
__device__ __forceinline__ float gelu_exact(float v) {
    return 0.5f * v * (1.f + erff(v * 0.70710678118654752f));
}

// grid-wide barrier: gridDim.x (131) <= #SMs (148), 1 block/SM -> co-resident, no deadlock.
__device__ __forceinline__ void gsync() {
    __syncthreads();
    if (threadIdx.x == 0) {
        unsigned gen = *(volatile unsigned*)&g_gen;
        __threadfence();
        if (atomicAdd(&g_cnt, 1u) == gridDim.x - 1u) {
            atomicExch(&g_cnt, 0u);
            __threadfence();
            atomicAdd(&g_gen, 1u);
        } else {
            while (*(volatile unsigned*)&g_gen == gen) { __nanosleep(32); }
        }
        __threadfence();
    }
    __syncthreads();
}

__global__ __launch_bounds__(NT_, 1) void k_fused(
    const float* __restrict__ x, const float* __restrict__ tokens,
    const float* __restrict__ x_pe, const float* __restrict__ conv_k,
    const float* __restrict__ bn_g, const float* __restrict__ bn_b,
    const float* __restrict__ bn_rm, const float* __restrict__ bn_rv,
    const float* __restrict__ fc_w1, const float* __restrict__ fc_w2,
    const float* __restrict__ ln1_g, const float* __restrict__ ln1_b,
    const float4* __restrict__ wqkv4,
    const float4* __restrict__ wout4, const float4* __restrict__ bout4,
    const float4* __restrict__ ln2g4, const float4* __restrict__ ln2b4,
    const float4* __restrict__ ffw1_4, const float4* __restrict__ ffb1_4,
    const float4* __restrict__ ffw2_4, const float4* __restrict__ ffb2_4,
    float4* __restrict__ out4)
{
    __shared__ __align__(16) char sm[20160];
    const int tid = threadIdx.x;
    const int b   = blockIdx.x;

    // ================= PHASE A: LN1 + QKV (blocks 0..128) + gating (129) =================
    if (b < 129) {
        float*  hs   = (float*)sm;                 // 2*196 floats
        float4* red  = (float4*)(sm + 1600);       // 3 slices * 128 gl * 2 rows
        float*  mrow = (float*)(sm + 13888);       // 2
        float*  rrow = (float*)(sm + 13896);       // 2

        const int tile  = b / 3;                   // 0..42
        const int chunk = b - tile * 3;
        const int base  = tile * 2;                // rows base, base+1 (guarded >= SEQ_)

        if (tid < 2 * D_) {
            int r = tid / D_, c = tid - r * D_;
            int row = base + r;
            hs[tid] = (row < SEQ_) ? x[row * D_ + c] : 0.f;
        }
        __syncthreads();

        const int warp = tid >> 5, lane = tid & 31;
        if (warp < 2) {
            float s1 = 0.f, s2 = 0.f;
            #pragma unroll
            for (int i = 0; i < 7; i++) {
                int c = lane + 32 * i;
                if (c < D_) { float v = hs[warp * D_ + c]; s1 += v; s2 += v * v; }
            }
            #pragma unroll
            for (int o = 16; o; o >>= 1) {
                s1 += __shfl_down_sync(0xffffffffu, s1, o);
                s2 += __shfl_down_sync(0xffffffffu, s2, o);
            }
            if (lane == 0) {
                float mean = s1 * (1.f / 196.f);
                float var  = s2 * (1.f / 196.f) - mean * mean;
                mrow[warp] = mean; rrow[warp] = rsqrtf(var + 1e-5f);
            }
        }
        __syncthreads();
        if (tid < 2 * D_) {
            int r = tid / D_, c = tid - r * D_;
            hs[tid] = (hs[tid] - mrow[r]) * rrow[r] * ln1_g[c] + ln1_b[c];
        }
        __syncthreads();

        const int gl = tid & 127;
        const int g  = chunk * 128 + gl;     // < 384
        const int s  = tid >> 7;             // K-slice 0..3, each 49
        float4 a0 = make_float4(0.f, 0.f, 0.f, 0.f);
        float4 a1 = make_float4(0.f, 0.f, 0.f, 0.f);

        const int kb = s * 49;
        const float4* W = wqkv4 + kb * NG_QKV + g;
        #pragma unroll 7
        for (int k = 0; k < 49; k++) {
            float4 w = W[k * NG_QKV];
            fma4(a0, hs[kb + k], w);
            fma4(a1, hs[D_ + kb + k], w);
        }
        if (s > 0) {
            red[((s - 1) * 128 + gl) * 2 + 0] = a0;
            red[((s - 1) * 128 + gl) * 2 + 1] = a1;
        }
        __syncthreads();
        if (s == 0) {
            float sc = (g < 128) ? 0.125f : 1.f;   // q pre-scale DH^-0.5
            #pragma unroll
            for (int ss = 0; ss < 3; ss++) {
                add4(a0, red[(ss * 128 + gl) * 2 + 0]);
                add4(a1, red[(ss * 128 + gl) * 2 + 1]);
            }
            a0.x *= sc; a0.y *= sc; a0.z *= sc; a0.w *= sc;
            a1.x *= sc; a1.y *= sc; a1.z *= sc; a1.w *= sc;
            if (base < SEQ_)     g_qkv4[base * NG_QKV + g]       = a0;
            if (base + 1 < SEQ_) g_qkv4[(base + 1) * NG_QKV + g] = a1;
        }
    } else if (b == 129) {
        // ---------------- gating ----------------
        float* b1s = (float*)sm;              // 64
        float* b2s = (float*)(sm + 256);      // 64
        float* hid = (float*)(sm + 512);      // 12
        float* cs  = (float*)(sm + 576);      // 64

        const int warp = tid >> 5, lane = tid & 31;
        const float k0 = conv_k[3], k1 = conv_k[4], k2 = conv_k[5];
        const float rm  = bn_rm[0];
        const float inv = rsqrtf(bn_rv[0] + 1e-5f) * bn_g[0];
        const float bb  = bn_b[0];

        for (int ch = warp; ch < NCH_; ch += 16) {
            const float* row = x_pe + ch * D_;
            float s = 0.f;
            for (int d = lane; d < D_; d += 32) {
                float xm = (d > 0)      ? row[d - 1] : 0.f;
                float xc = row[d];
                float xp = (d < D_ - 1) ? row[d + 1] : 0.f;
                float conv = k0 * xm + k1 * xc + k2 * xp;
                float bn = (conv - rm) * inv + bb;
                float av = fmaxf(bn, 0.f);
                g_a[ch * D_ + d] = av;
                s += av;
            }
            #pragma unroll
            for (int o = 16; o; o >>= 1) s += __shfl_down_sync(0xffffffffu, s, o);
            if (lane == 0) b1s[ch] = s * (1.f / 196.f);
        }
        __syncthreads();

        if (tid < NCH_) {
            const float bi = b1s[tid];
            float mx = -1e30f, mn = 1e30f;
            int cnt_nonpos = 0, rank = 0;
            #pragma unroll 8
            for (int j = 0; j < NCH_; j++) {
                float bj = b1s[j];
                mx = fmaxf(mx, bj); mn = fminf(mn, bj);
                if (bj <= 0.f) cnt_nonpos++;
                if (bj < bi || (bj == bi && j < tid)) rank++;
            }
            int middle = (mx < 0.f || mn > 0.f) ? 32 : (mx > 0.f ? cnt_nonpos : 0);
            float b2;
            if (rank < middle) {
                float ls = (float)middle;
                b2 = bi - 1.f / (1.f + powf(ls, bi));
            } else {
                float le = (float)(NCH_ - middle);
                b2 = bi + 1.f / (1.f + powf(le, -bi));
            }
            b2s[tid] = b2;
        }
        __syncthreads();
        if (tid < 12) {
            float s = 0.f;
            #pragma unroll 8
            for (int i = 0; i < NCH_; i++) s += b2s[i] * fc_w1[i * 12 + tid];
            hid[tid] = fmaxf(s, 0.f);
        }
        __syncthreads();
        if (tid < NCH_) {
            float s = 0.f;
            #pragma unroll
            for (int j = 0; j < 12; j++) s += hid[j] * fc_w2[j * NCH_ + tid];
            cs[tid] = 1.f / (1.f + expf(-s));
        }
        __syncthreads();
        float* xatt = (float*)g_xatt4;
        for (int idx = tid; idx < NCH_ * D_; idx += NT_)
            xatt[idx] = g_a[idx] * cs[idx / D_];
        for (int d = tid; d < D_; d += NT_)
            xatt[NCH_ * D_ + d] = tokens[d];
    }
    gsync();   // the ONLY grid barrier

    if (b >= 130) return;

    // generation tag for pairwise flags (stable within this launch, monotonic across replays)
    __shared__ unsigned genS;
    if (tid == 0) genS = *(volatile unsigned*)&g_gen;
    __syncthreads();
    const unsigned gen = genS;

    // ================= PHASE B: pairwise per-row pipeline =================
    // master = block n (n<65): heads 0-3, outproj K[0,256), FF1 cols[0,392), FF2 K[0,392)
    // helper = block 65+n   : heads 4-7, outproj K[256,512), FF1 cols[392,784), FF2 K[392,784)
    const bool isM = (b < SEQ_);
    const int  n    = isM ? b : (b - SEQ_);
    const int  hoff = isM ? 0 : 4;       // head offset
    const int  koff = isM ? 0 : 256;     // outproj K offset (scalar rows)
    const int  coff = isM ? 0 : 98;      // FF1 col offset (f4 units)
    const int  toff = isM ? 0 : 392;     // FF2 K offset (scalar rows)
    const float* qkv = (const float*)g_qkv4;

    float*  qs    = (float*)sm;                // 512 f   [0,2048)
    float*  scs   = (float*)(sm + 2048);       // 4*66 f  [2048,3104)
    float*  sinvp = (float*)(sm + 3104);       // 4       [3104,3120)
    float*  avp   = (float*)(sm + 3136);       // 512 f   [3136,5184)
    float*  os    = (float*)(sm + 5184);       // 256 f   [5184,6208)
    float4* red   = (float4*)(sm + 6208);      // 7*49 f4 [6208,11696)
    float4* x2s   = (float4*)(sm + 11696);     // 49 f4   [11696,12480)
    float4* h2s   = (float4*)(sm + 12480);     // 49 f4   [12480,13264)
    float*  p1    = (float*)(sm + 13264);      // 49
    float*  p2    = (float*)(sm + 13460);      // 49
    float*  stats = (float*)(sm + 13656);      // 2
    float4* ts4   = (float4*)(sm + 13664);     // 98 f4   [13664,15232)
    float4* red1  = (float4*)(sm + 15232);     // 3*98 f4 [15232,19936)

    // ---- attention for 4 heads: h_loc = tid>>7, r = tid&127 ----
    const int h_loc = tid >> 7;                // 0..3
    const int r     = tid & 127;
    const int hglb  = hoff + h_loc;
    qs[tid] = qkv[n * 1536 + tid];             // full q row (only own heads used)
    __syncthreads();

    if (r < SEQ_) {
        const float* qh = qs + hglb * DH_;
        const float4* kr = (const float4*)(qkv + r * 1536 + INNER_ + hglb * DH_);
        float s = 0.f;
        #pragma unroll
        for (int i = 0; i < 16; i++) {
            float4 k4 = kr[i];
            s += qh[4*i] * k4.x + qh[4*i+1] * k4.y + qh[4*i+2] * k4.z + qh[4*i+3] * k4.w;
        }
        scs[h_loc * 66 + r] = s;
    }
    __syncthreads();
    // softmax per head: warp w (0..3) handles head w
    if (tid < 128) {
        const int w = tid >> 5, lane = tid & 31;
        float e0 = scs[w * 66 + lane], e1 = scs[w * 66 + lane + 32];
        float e2 = (lane == 0) ? scs[w * 66 + 64] : -1e30f;
        float mx = fmaxf(fmaxf(e0, e1), e2);
        #pragma unroll
        for (int o = 16; o; o >>= 1) mx = fmaxf(mx, __shfl_down_sync(0xffffffffu, mx, o));
        mx = __shfl_sync(0xffffffffu, mx, 0);
        float x0 = expf(e0 - mx), x1 = expf(e1 - mx);
        float x2v = (lane == 0) ? expf(scs[w * 66 + 64] - mx) : 0.f;
        scs[w * 66 + lane] = x0; scs[w * 66 + lane + 32] = x1;
        if (lane == 0) scs[w * 66 + 64] = x2v;
        float s = x0 + x1 + x2v;
        #pragma unroll
        for (int o = 16; o; o >>= 1) s += __shfl_down_sync(0xffffffffu, s, o);
        if (lane == 0) sinvp[w] = 1.f / s;
    }
    __syncthreads();
    // AV split over K-halves: d = r&63, mh = r>>6
    {
        const int d = r & 63, mh = r >> 6;
        const float* vb = qkv + 2 * INNER_ + hglb * DH_ + d;
        const float* p  = scs + h_loc * 66;
        const int m0 = mh ? 33 : 0;
        const int m1 = mh ? SEQ_ : 33;
        float acc = 0.f;
        #pragma unroll 8
        for (int m = m0; m < m1; m++) acc += p[m] * vb[m * 1536];
        avp[h_loc * 128 + r] = acc;
    }
    __syncthreads();
    if (tid < 256) {
        const int hl = tid >> 6, d = tid & 63;
        os[hl * 64 + d] = (avp[hl * 128 + d] + avp[hl * 128 + 64 + d]) * sinvp[hl];
    }
    __syncthreads();

    // ---- outproj partial over K-half [koff, koff+256): 8 slices of 32 ----
    const int s8 = tid >> 6;                   // 0..7
    const int g  = tid & 63;                   // <49 active
    const bool act = (g < NG_D);
    float4 vacc = make_float4(0.f, 0.f, 0.f, 0.f);
    if (act) {
        const int kb = s8 * 32;
        const float4* W = wout4 + (koff + kb) * NG_D + g;
        const float* hb = os + kb;
        #pragma unroll 8
        for (int k = 0; k < 32; k++) fma4(vacc, hb[k], W[k * NG_D]);
        if (s8 > 0) red[(s8 - 1) * NG_D + g] = vacc;
    }
    __syncthreads();

    if (!isM) {
        // helper: publish outproj partial, wait for h2, then FF half
        if (act && s8 == 0) {
            #pragma unroll
            for (int ss = 0; ss < 7; ss++) add4(vacc, red[ss * NG_D + g]);
            g_p1[n * NG_D + g] = vacc;
        }
        __syncthreads();
        if (tid == 0) { __threadfence(); *(volatile unsigned*)&g_fA[n] = gen; }
        // wait for LN2 output
        if (tid == 0) {
            while (*(volatile unsigned*)&g_fB[n] < gen) { __nanosleep(32); }
            __threadfence();
        }
        __syncthreads();
        if (tid < NG_D) h2s[tid] = g_h2g[n * NG_D + tid];
        __syncthreads();
    } else {
        // master: wait for helper partial, combine, residuals, LN2
        if (tid == 0) {
            while (*(volatile unsigned*)&g_fA[n] < gen) { __nanosleep(32); }
            __threadfence();
        }
        __syncthreads();
        if (act && s8 == 0) {
            #pragma unroll
            for (int ss = 0; ss < 7; ss++) add4(vacc, red[ss * NG_D + g]);
            add4(vacc, g_p1[n * NG_D + g]);
            float4 bo = bout4[g];
            float4 xv = ((const float4*)x)[n * NG_D + g];
            float4 xa = g_xatt4[n * NG_D + g];
            vacc.x += bo.x + xv.x + xa.x;
            vacc.y += bo.y + xv.y + xa.y;
            vacc.z += bo.z + xv.z + xa.z;
            vacc.w += bo.w + xv.w + xa.w;
            x2s[g] = vacc;
            p1[g] = vacc.x + vacc.y + vacc.z + vacc.w;
            p2[g] = vacc.x*vacc.x + vacc.y*vacc.y + vacc.z*vacc.z + vacc.w*vacc.w;
        }
        __syncthreads();
        if (tid < 32) {
            float t1 = 0.f, t2 = 0.f;
            for (int i = tid; i < NG_D; i += 32) { t1 += p1[i]; t2 += p2[i]; }
            #pragma unroll
            for (int o = 16; o; o >>= 1) {
                t1 += __shfl_down_sync(0xffffffffu, t1, o);
                t2 += __shfl_down_sync(0xffffffffu, t2, o);
            }
            if (tid == 0) {
                float mean = t1 * (1.f / 196.f);
                float var  = t2 * (1.f / 196.f) - mean * mean;
                stats[0] = mean; stats[1] = rsqrtf(var + 1e-5f);
            }
        }
        __syncthreads();
        if (tid < NG_D) {
            float m = stats[0], rs = stats[1];
            float4 v = x2s[tid], gg = ln2g4[tid], bb = ln2b4[tid], hh;
            hh.x = (v.x - m) * rs * gg.x + bb.x;
            hh.y = (v.y - m) * rs * gg.y + bb.y;
            hh.z = (v.z - m) * rs * gg.z + bb.z;
            hh.w = (v.w - m) * rs * gg.w + bb.w;
            h2s[tid] = hh;
            g_h2g[n * NG_D + tid] = hh;
        }
        __syncthreads();
        if (tid == 0) { __threadfence(); *(volatile unsigned*)&g_fB[n] = gen; }
    }

    // ---- FF1 half: cols [coff, coff+98) f4; c = tid&127 (<98), ks = tid>>7 (0..3) ----
    {
        const int c = tid & 127, ks = tid >> 7;
        float4 facc = make_float4(0.f, 0.f, 0.f, 0.f);
        if (c < 98) {
            const float* hh = (const float*)h2s;   // 196 floats
            const int kb = ks * 49;
            const float4* W = ffw1_4 + kb * NG_MLP + coff + c;
            #pragma unroll 7
            for (int k = 0; k < 49; k++) fma4(facc, hh[kb + k], W[k * NG_MLP]);
            if (ks > 0) red1[(ks - 1) * 98 + c] = facc;
        }
        __syncthreads();
        if (c < 98 && ks == 0) {
            #pragma unroll
            for (int ss = 0; ss < 3; ss++) add4(facc, red1[ss * 98 + c]);
            float4 fb = ffb1_4[coff + c], t;
            t.x = gelu_exact(facc.x + fb.x);
            t.y = gelu_exact(facc.y + fb.y);
            t.z = gelu_exact(facc.z + fb.z);
            t.w = gelu_exact(facc.w + fb.w);
            ts4[c] = t;
        }
    }
    __syncthreads();

    // ---- FF2 partial over own t-half: 8 slices of 49 ----
    float4 oacc = make_float4(0.f, 0.f, 0.f, 0.f);
    if (act) {
        const int kb = s8 * 49;
        const float* tf = (const float*)ts4;   // 392 floats
        const float4* W = ffw2_4 + (toff + kb) * NG_D + g;
        #pragma unroll 7
        for (int k = 0; k < 49; k++) fma4(oacc, tf[kb + k], W[k * NG_D]);
        if (s8 > 0) red[(s8 - 1) * NG_D + g] = oacc;
    }
    __syncthreads();

    if (!isM) {
        if (act && s8 == 0) {
            #pragma unroll
            for (int ss = 0; ss < 7; ss++) add4(oacc, red[ss * NG_D + g]);
            g_p2[n * NG_D + g] = oacc;
        }
        __syncthreads();
        if (tid == 0) { __threadfence(); *(volatile unsigned*)&g_fC[n] = gen; }
    } else {
        if (tid == 0) {
            while (*(volatile unsigned*)&g_fC[n] < gen) { __nanosleep(32); }
            __threadfence();
        }
        __syncthreads();
        if (act && s8 == 0) {
            #pragma unroll
            for (int ss = 0; ss < 7; ss++) add4(oacc, red[ss * NG_D + g]);
            add4(oacc, g_p2[n * NG_D + g]);
            float4 fb = ffb2_4[g], x2 = x2s[g];
            oacc.x += fb.x + x2.x; oacc.y += fb.y + x2.y;
            oacc.z += fb.z + x2.z; oacc.w += fb.w + x2.w;
            out4[n * NG_D + g] = oacc;
        }
    }
}

// ============================================================
extern "C" void kernel_launch(void* const* d_in, const int* in_sizes, int n_in,
                              void* d_out, int out_size)
{
    const float* x      = (const float*)d_in[0];
    const float* tokens = (const float*)d_in[1];
    const float* x_pe   = (const float*)d_in[2];
    const float* conv_k = (const float*)d_in[3];
    const float* bn_g   = (const float*)d_in[4];
    const float* bn_b   = (const float*)d_in[5];
    const float* bn_rm  = (const float*)d_in[6];
    const float* bn_rv  = (const float*)d_in[7];
    const float* fc_w1  = (const float*)d_in[8];
    const float* fc_w2  = (const float*)d_in[9];
    const float* ln1_g  = (const float*)d_in[10];
    const float* ln1_b  = (const float*)d_in[11];
    const float* ln2_g  = (const float*)d_in[12];
    const float* ln2_b  = (const float*)d_in[13];
    const float* w_qkv  = (const float*)d_in[14];
    const float* w_out  = (const float*)d_in[15];
    const float* b_out  = (const float*)d_in[16];
    const float* ff_w1  = (const float*)d_in[17];
    const float* ff_b1  = (const float*)d_in[18];
    const float* ff_w2  = (const float*)d_in[19];
    const float* ff_b2  = (const float*)d_in[20];

    k_fused<<<GRID_, NT_>>>(x, tokens, x_pe, conv_k, bn_g, bn_b, bn_rm, bn_rv,
                            fc_w1, fc_w2, ln1_g, ln1_b,
                            (const float4*)w_qkv,
                            (const float4*)w_out, (const float4*)b_out,
                            (const float4*)ln2_g, (const float4*)ln2_b,
                            (const float4*)ff_w1, (const float4*)ff_b1,
                            (const float4*)ff_w2, (const float4*)ff_b2,
                            (float4*)d_out);
}